// round 2
// baseline (speedup 1.0000x reference)
#include <cuda_runtime.h>
#include <cuda_bf16.h>
#include <cstdint>

// ============================================================================
// Scratch (static __device__ arrays — no allocations allowed)
// ============================================================================
#define KROWS 8192
#define NROWS 8192
#define MDIM  64

__device__ __nv_bfloat16 g_Xb[KROWS * MDIM];            // x in bf16
__device__ __nv_bfloat16 g_Cb[NROWS * MDIM];            // x_basis in bf16
__device__ float  g_xs[KROWS];                          // -log2e * ||x_i||^2
__device__ __align__(16) float2 g_cw[NROWS];            // { -log2e*||c_j||^2 , w_j }
__device__ float  g_partial[2][KROWS];                  // j-split partial logits

#define LOG2E 1.4426950408889634f

// ============================================================================
// mma.sync m16n8k16 bf16 (baseline PTX, works on sm_100 non-'a' target)
// ============================================================================
__device__ __forceinline__ void mma16816(float* c, const uint32_t* a,
                                         uint32_t b0, uint32_t b1) {
    asm volatile(
        "mma.sync.aligned.m16n8k16.row.col.f32.bf16.bf16.f32 "
        "{%0,%1,%2,%3}, {%4,%5,%6,%7}, {%8,%9}, {%0,%1,%2,%3};"
        : "+f"(c[0]), "+f"(c[1]), "+f"(c[2]), "+f"(c[3])
        : "r"(a[0]), "r"(a[1]), "r"(a[2]), "r"(a[3]), "r"(b0), "r"(b1));
}

// ============================================================================
// K1: convert to bf16, compute pre-scaled norms, pack (cs, w)
// ============================================================================
__global__ void prep_kernel(const float* __restrict__ x,
                            const float* __restrict__ xb,
                            const float* __restrict__ w) {
    int rowg = blockIdx.x * 8 + (threadIdx.x >> 5);
    int lid  = threadIdx.x & 31;
    bool isb = rowg >= KROWS;
    int r    = isb ? rowg - KROWS : rowg;
    const float* src = isb ? xb : x;

    float2 v = ((const float2*)(src + (size_t)r * MDIM))[lid];
    __nv_bfloat162 bv = __float22bfloat162_rn(v);
    __nv_bfloat16* dst = isb ? g_Cb : g_Xb;
    ((__nv_bfloat162*)(dst + (size_t)r * MDIM))[lid] = bv;

    float nrm = v.x * v.x + v.y * v.y;
    #pragma unroll
    for (int o = 16; o; o >>= 1) nrm += __shfl_xor_sync(0xFFFFFFFFu, nrm, o);

    if (lid == 0) {
        float s = -LOG2E * nrm;
        if (isb) g_cw[r] = make_float2(s, w[r]);
        else     g_xs[r] = s;
    }
}

// ============================================================================
// K2: register-tiled bf16 GEMM (mma.sync) + fused exp/weighted-sum epilogue
// grid = (64 i-tiles, 2 j-splits), 256 threads = 8 warps
// warp grid: 4 warp-rows (32 rows each) x 2 warp-cols (64 cols each)
// ============================================================================
#define TI 128
#define TJ 128
#define TPC 32              // j-tiles per CTA: 4096/128

__global__ void __launch_bounds__(256, 1) rbf_main_kernel() {
    __shared__ float red[2][TI];

    const int tid = threadIdx.x;
    const int wid = tid >> 5;
    const int lid = tid & 31;
    const int wrow = wid >> 1;           // 0..3
    const int wc   = wid & 1;            // 0..1
    const int g    = lid >> 2;           // 0..7  (row group within frag)
    const int q2   = (lid & 3) * 2;      // 0,2,4,6 (col/k pair base)

    const int i0    = blockIdx.x * TI;
    const int js    = blockIdx.y;
    const int jbase = js * (TJ * TPC);

    // ---- persistent A fragments: rows [i0 + wrow*32, +32), K=64 ----
    uint32_t a[2][4][4];                 // [mt][ks][reg]
    {
        const __nv_bfloat16* Ap = g_Xb + (size_t)(i0 + wrow * 32) * MDIM;
        #pragma unroll
        for (int mt = 0; mt < 2; mt++) {
            #pragma unroll
            for (int ks = 0; ks < 4; ks++) {
                int r0 = mt * 16 + g;
                int kk = ks * 16 + q2;
                a[mt][ks][0] = *(const uint32_t*)(Ap + (size_t)r0 * MDIM + kk);
                a[mt][ks][1] = *(const uint32_t*)(Ap + (size_t)(r0 + 8) * MDIM + kk);
                a[mt][ks][2] = *(const uint32_t*)(Ap + (size_t)r0 * MDIM + kk + 8);
                a[mt][ks][3] = *(const uint32_t*)(Ap + (size_t)(r0 + 8) * MDIM + kk + 8);
            }
        }
    }

    // per-thread row exponents (4 rows: mt*16 + g + {0,8})
    float xs[2][2];
    #pragma unroll
    for (int mt = 0; mt < 2; mt++) {
        xs[mt][0] = g_xs[i0 + wrow * 32 + mt * 16 + g];
        xs[mt][1] = g_xs[i0 + wrow * 32 + mt * 16 + g + 8];
    }

    const float C2 = 2.0f * LOG2E;
    float acc[2][2] = {{0.f, 0.f}, {0.f, 0.f}};   // [mt][half] row partial sums

    for (int t = 0; t < TPC; t++) {
        const int j0 = jbase + t * TJ + wc * 64;  // this warp's 64-col slice
        const __nv_bfloat16* Bp = g_Cb + (size_t)j0 * MDIM;

        float c[2][8][4];
        #pragma unroll
        for (int mt = 0; mt < 2; mt++)
            #pragma unroll
            for (int nt = 0; nt < 8; nt++)
                #pragma unroll
                for (int cc = 0; cc < 4; cc++) c[mt][nt][cc] = 0.f;

        #pragma unroll
        for (int ks = 0; ks < 4; ks++) {
            const int kk = ks * 16 + q2;
            uint32_t b[8][2];
            #pragma unroll
            for (int nt = 0; nt < 8; nt++) {
                const __nv_bfloat16* bp = Bp + (size_t)(nt * 8 + g) * MDIM + kk;
                b[nt][0] = *(const uint32_t*)(bp);
                b[nt][1] = *(const uint32_t*)(bp + 8);
            }
            #pragma unroll
            for (int nt = 0; nt < 8; nt++) {
                mma16816(c[0][nt], a[0][ks], b[nt][0], b[nt][1]);
                mma16816(c[1][nt], a[1][ks], b[nt][0], b[nt][1]);
            }
        }

        // ---- epilogue: acc += w_j * 2^(2*log2e*S + xs_i + cs_j) ----
        #pragma unroll
        for (int nt = 0; nt < 8; nt++) {
            // cols j0 + nt*8 + q2 + {0,1}: (cs0,w0,cs1,w1) as one 16B load
            float4 cw = *(const float4*)(&g_cw[j0 + nt * 8 + q2]);
            #pragma unroll
            for (int mt = 0; mt < 2; mt++) {
                #pragma unroll
                for (int h = 0; h < 2; h++) {
                    float base0 = xs[mt][h] + cw.x;
                    float base1 = xs[mt][h] + cw.z;
                    float s0 = c[mt][nt][h * 2 + 0];
                    float s1 = c[mt][nt][h * 2 + 1];
                    float t0 = fmaf(s0, C2, base0);
                    float t1 = fmaf(s1, C2, base1);
                    float p0, p1;
                    asm("ex2.approx.f32 %0, %1;" : "=f"(p0) : "f"(t0));
                    asm("ex2.approx.f32 %0, %1;" : "=f"(p1) : "f"(t1));
                    acc[mt][h] = fmaf(p0, cw.y, acc[mt][h]);
                    acc[mt][h] = fmaf(p1, cw.w, acc[mt][h]);
                }
            }
        }
    }

    // ---- reduce cols within quad (lanes sharing g hold disjoint cols) ----
    #pragma unroll
    for (int mt = 0; mt < 2; mt++)
        #pragma unroll
        for (int h = 0; h < 2; h++) {
            float v = acc[mt][h];
            v += __shfl_xor_sync(0xFFFFFFFFu, v, 1);
            v += __shfl_xor_sync(0xFFFFFFFFu, v, 2);
            acc[mt][h] = v;
        }

    if ((lid & 3) == 0) {
        #pragma unroll
        for (int mt = 0; mt < 2; mt++)
            #pragma unroll
            for (int h = 0; h < 2; h++)
                red[wc][wrow * 32 + mt * 16 + g + h * 8] = acc[mt][h];
    }
    __syncthreads();
    if (tid < TI) g_partial[js][i0 + tid] = red[0][tid] + red[1][tid];
}

// ============================================================================
// K3: combine partials + bias + sigmoid
// ============================================================================
__global__ void finish_kernel(const float* __restrict__ b, float* __restrict__ out) {
    int i = blockIdx.x * 256 + threadIdx.x;
    float z = g_partial[0][i] + g_partial[1][i] + b[0];
    out[i] = 1.0f / (1.0f + __expf(-z));
}

// ============================================================================
// kernel_launch
// ============================================================================
extern "C" void kernel_launch(void* const* d_in, const int* in_sizes, int n_in,
                              void* d_out, int out_size) {
    const float* x  = (const float*)d_in[0];
    const float* xb = (const float*)d_in[1];
    const float* w  = (const float*)d_in[2];
    const float* b  = (const float*)d_in[3];
    float* out = (float*)d_out;

    prep_kernel<<<(KROWS + NROWS) / 8, 256>>>(x, xb, w);
    dim3 grid(KROWS / TI, 2);
    rbf_main_kernel<<<grid, 256>>>();
    finish_kernel<<<KROWS / 256, 256>>>(b, out);
}

// round 4
// speedup vs baseline: 1.0394x; 1.0394x over previous
#include <cuda_runtime.h>
#include <cuda_bf16.h>
#include <cstdint>

// ============================================================================
// Scratch (static __device__ arrays — no allocations allowed)
// ============================================================================
#define KROWS 8192
#define NROWS 8192
#define MDIM  64

__device__ __nv_bfloat16 g_Xb[KROWS * MDIM];            // x in bf16
__device__ __nv_bfloat16 g_Cb[NROWS * MDIM];            // x_basis in bf16
__device__ float  g_xs[KROWS];                          // -log2e * ||x_i||^2
__device__ __align__(16) float2 g_cw[NROWS];            // { -log2e*||c_j||^2 , w_j }
__device__ float  g_partial[2][KROWS];                  // j-split partial logits

#define LOG2E 1.4426950408889634f

// ============================================================================
// mma.sync m16n8k16 bf16 (baseline PTX — sm_100 non-'a' target OK)
// ============================================================================
__device__ __forceinline__ void mma16816(float* c, const uint32_t* a,
                                         uint32_t b0, uint32_t b1) {
    asm volatile(
        "mma.sync.aligned.m16n8k16.row.col.f32.bf16.bf16.f32 "
        "{%0,%1,%2,%3}, {%4,%5,%6,%7}, {%8,%9}, {%0,%1,%2,%3};"
        : "+f"(c[0]), "+f"(c[1]), "+f"(c[2]), "+f"(c[3])
        : "r"(a[0]), "r"(a[1]), "r"(a[2]), "r"(a[3]), "r"(b0), "r"(b1));
}

// Packed f16x2 exp2: halves MUFU issue count vs two ex2.approx.f32.
// f16 flush-to-zero at 2^-24 only hits sq<17 tail pairs (phi<=1e-7): harmless.
__device__ __forceinline__ void exp2_f16x2(float t0, float t1,
                                           float& p0, float& p1) {
    uint32_t h, e;
    asm("cvt.rn.f16x2.f32 %0, %1, %2;" : "=r"(h) : "f"(t1), "f"(t0)); // hi=t1, lo=t0
    asm("ex2.approx.f16x2 %0, %1;" : "=r"(e) : "r"(h));
    asm("{\n\t.reg .b16 lo, hi;\n\t"
        "mov.b32 {lo, hi}, %2;\n\t"
        "cvt.f32.f16 %0, lo;\n\t"
        "cvt.f32.f16 %1, hi;\n\t}"
        : "=f"(p0), "=f"(p1) : "r"(e));
}

// ============================================================================
// K1: convert to bf16, compute pre-scaled norms, pack (cs, w)
// 512 blocks x 256 thr, each warp handles 4 rows (amortizes launch overhead)
// ============================================================================
__global__ void prep_kernel(const float* __restrict__ x,
                            const float* __restrict__ xb,
                            const float* __restrict__ w) {
    const int lid = threadIdx.x & 31;
    #pragma unroll
    for (int pass = 0; pass < 4; pass++) {
        int rowg = blockIdx.x * 8 + (threadIdx.x >> 5) + pass * 4096;
        bool isb = rowg >= KROWS;
        int r    = isb ? rowg - KROWS : rowg;
        const float* src = isb ? xb : x;

        float2 v = ((const float2*)(src + (size_t)r * MDIM))[lid];
        __nv_bfloat162 bv = __float22bfloat162_rn(v);
        __nv_bfloat16* dst = isb ? g_Cb : g_Xb;
        ((__nv_bfloat162*)(dst + (size_t)r * MDIM))[lid] = bv;

        float nrm = v.x * v.x + v.y * v.y;
        #pragma unroll
        for (int o = 16; o; o >>= 1) nrm += __shfl_xor_sync(0xFFFFFFFFu, nrm, o);

        if (lid == 0) {
            float s = -LOG2E * nrm;
            if (isb) g_cw[r] = make_float2(s, w[r]);
            else     g_xs[r] = s;
        }
    }
}

// ============================================================================
// K2: register-tiled bf16 GEMM (mma.sync) + fused exp/weighted-sum epilogue
// grid = (64 i-tiles, 2 j-splits), 512 threads = 16 warps
// warp grid: 4 warp-rows (32 rows each) x 4 warp-cols (32 cols each)
// ============================================================================
#define TI 128
#define TJ 128
#define TPC 32              // j-tiles per CTA: 4096/128

__global__ void __launch_bounds__(512, 1) rbf_main_kernel() {
    __shared__ float red[4][TI];

    const int tid = threadIdx.x;
    const int wid = tid >> 5;
    const int lid = tid & 31;
    const int wrow = wid >> 2;           // 0..3 (32-row slice)
    const int wc   = wid & 3;            // 0..3 (32-col slice)
    const int g    = lid >> 2;           // 0..7
    const int q2   = (lid & 3) * 2;      // 0,2,4,6

    const int i0    = blockIdx.x * TI;
    const int js    = blockIdx.y;
    const int jbase = js * (TJ * TPC);

    // ---- persistent A fragments: rows [i0 + wrow*32, +32), K=64 ----
    uint32_t a[2][4][4];                 // [mt][ks][reg]
    {
        const __nv_bfloat16* Ap = g_Xb + (size_t)(i0 + wrow * 32) * MDIM;
        #pragma unroll
        for (int mt = 0; mt < 2; mt++) {
            #pragma unroll
            for (int ks = 0; ks < 4; ks++) {
                int r0 = mt * 16 + g;
                int kk = ks * 16 + q2;
                a[mt][ks][0] = *(const uint32_t*)(Ap + (size_t)r0 * MDIM + kk);
                a[mt][ks][1] = *(const uint32_t*)(Ap + (size_t)(r0 + 8) * MDIM + kk);
                a[mt][ks][2] = *(const uint32_t*)(Ap + (size_t)r0 * MDIM + kk + 8);
                a[mt][ks][3] = *(const uint32_t*)(Ap + (size_t)(r0 + 8) * MDIM + kk + 8);
            }
        }
    }

    // per-thread row exponents (4 rows: mt*16 + g + {0,8})
    float xs[2][2];
    #pragma unroll
    for (int mt = 0; mt < 2; mt++) {
        xs[mt][0] = g_xs[i0 + wrow * 32 + mt * 16 + g];
        xs[mt][1] = g_xs[i0 + wrow * 32 + mt * 16 + g + 8];
    }

    const float C2 = 2.0f * LOG2E;
    float acc[2][2] = {{0.f, 0.f}, {0.f, 0.f}};   // [mt][half]

    for (int t = 0; t < TPC; t++) {
        const int j0 = jbase + t * TJ + wc * 32;  // this warp's 32-col slice
        const __nv_bfloat16* Bp = g_Cb + (size_t)j0 * MDIM;

        // double-buffered B fragments across k-steps
        uint32_t b[2][4][2];
        #pragma unroll
        for (int nt = 0; nt < 4; nt++) {
            const __nv_bfloat16* bp = Bp + (size_t)(nt * 8 + g) * MDIM + q2;
            b[0][nt][0] = *(const uint32_t*)(bp);
            b[0][nt][1] = *(const uint32_t*)(bp + 8);
        }

        float4 cwv[4];
        float c[2][4][4];
        #pragma unroll
        for (int mt = 0; mt < 2; mt++)
            #pragma unroll
            for (int nt = 0; nt < 4; nt++)
                #pragma unroll
                for (int cc = 0; cc < 4; cc++) c[mt][nt][cc] = 0.f;

        #pragma unroll
        for (int ks = 0; ks < 4; ks++) {
            const int cur = ks & 1, nxt = cur ^ 1;
            if (ks < 3) {
                const int kk = (ks + 1) * 16 + q2;
                #pragma unroll
                for (int nt = 0; nt < 4; nt++) {
                    const __nv_bfloat16* bp = Bp + (size_t)(nt * 8 + g) * MDIM + kk;
                    b[nxt][nt][0] = *(const uint32_t*)(bp);
                    b[nxt][nt][1] = *(const uint32_t*)(bp + 8);
                }
            }
            if (ks == 0) {   // early cw prefetch: ~3 mma-groups of latency cover
                #pragma unroll
                for (int nt = 0; nt < 4; nt++)
                    cwv[nt] = *(const float4*)(&g_cw[j0 + nt * 8 + q2]);
            }
            #pragma unroll
            for (int nt = 0; nt < 4; nt++) {
                mma16816(c[0][nt], a[0][ks], b[cur][nt][0], b[cur][nt][1]);
                mma16816(c[1][nt], a[1][ks], b[cur][nt][0], b[cur][nt][1]);
            }
        }

        // ---- epilogue: acc += w_j * 2^(2*log2e*S + xs_i + cs_j) ----
        #pragma unroll
        for (int nt = 0; nt < 4; nt++) {
            const float4 cw = cwv[nt];
            #pragma unroll
            for (int mt = 0; mt < 2; mt++) {
                #pragma unroll
                for (int h = 0; h < 2; h++) {
                    const float base = xs[mt][h];
                    float t0 = fmaf(c[mt][nt][h * 2 + 0], C2, base + cw.x);
                    float t1 = fmaf(c[mt][nt][h * 2 + 1], C2, base + cw.z);
                    float p0, p1;
                    exp2_f16x2(t0, t1, p0, p1);
                    acc[mt][h] = fmaf(p0, cw.y, acc[mt][h]);
                    acc[mt][h] = fmaf(p1, cw.w, acc[mt][h]);
                }
            }
        }
    }

    // ---- reduce cols within quad (lanes in a quad hold disjoint cols) ----
    #pragma unroll
    for (int mt = 0; mt < 2; mt++)
        #pragma unroll
        for (int h = 0; h < 2; h++) {
            float v = acc[mt][h];
            v += __shfl_xor_sync(0xFFFFFFFFu, v, 1);
            v += __shfl_xor_sync(0xFFFFFFFFu, v, 2);
            acc[mt][h] = v;
        }

    if ((lid & 3) == 0) {
        #pragma unroll
        for (int mt = 0; mt < 2; mt++)
            #pragma unroll
            for (int h = 0; h < 2; h++)
                red[wc][wrow * 32 + mt * 16 + g + h * 8] = acc[mt][h];
    }
    __syncthreads();
    if (tid < TI)
        g_partial[js][i0 + tid] =
            (red[0][tid] + red[1][tid]) + (red[2][tid] + red[3][tid]);
}

// ============================================================================
// K3: combine partials + bias + sigmoid
// ============================================================================
__global__ void finish_kernel(const float* __restrict__ b, float* __restrict__ out) {
    int i = blockIdx.x * 256 + threadIdx.x;
    float z = g_partial[0][i] + g_partial[1][i] + b[0];
    out[i] = 1.0f / (1.0f + __expf(-z));
}

// ============================================================================
// kernel_launch
// ============================================================================
extern "C" void kernel_launch(void* const* d_in, const int* in_sizes, int n_in,
                              void* d_out, int out_size) {
    const float* x  = (const float*)d_in[0];
    const float* xb = (const float*)d_in[1];
    const float* w  = (const float*)d_in[2];
    const float* b  = (const float*)d_in[3];
    float* out = (float*)d_out;

    prep_kernel<<<512, 256>>>(x, xb, w);
    dim3 grid(KROWS / TI, 2);
    rbf_main_kernel<<<grid, 512>>>();
    finish_kernel<<<KROWS / 256, 256>>>(b, out);
}

// round 6
// speedup vs baseline: 1.7554x; 1.6888x over previous
#include <cuda_runtime.h>
#include <cuda_bf16.h>
#include <cstdint>

// ============================================================================
// Scratch (static __device__ arrays — no allocations allowed)
// ============================================================================
#define KROWS 8192
#define NROWS 8192
#define MDIM  64

__device__ __nv_bfloat16 g_Xb[KROWS * MDIM];            // x in bf16
__device__ __nv_bfloat16 g_Cb[NROWS * MDIM];            // x_basis in bf16
__device__ float  g_xs[KROWS];                          // -log2e * ||x_i||^2
__device__ __align__(16) float2 g_cw[NROWS];            // { -log2e*||c_j||^2 , w_j }
__device__ float  g_partial[2][KROWS];                  // j-split partial logits

#define LOG2E 1.4426950408889634f

// ============================================================================
// PTX helpers (baseline features only — sm_100 non-'a' target)
// ============================================================================
__device__ __forceinline__ uint32_t smem_u32(const void* p) {
    uint32_t a;
    asm("{ .reg .u64 t; cvta.to.shared.u64 t, %1; cvt.u32.u64 %0, t; }"
        : "=r"(a) : "l"(p));
    return a;
}

__device__ __forceinline__ void mma16816(float* c, const uint32_t* a,
                                         uint32_t b0, uint32_t b1) {
    asm volatile(
        "mma.sync.aligned.m16n8k16.row.col.f32.bf16.bf16.f32 "
        "{%0,%1,%2,%3}, {%4,%5,%6,%7}, {%8,%9}, {%0,%1,%2,%3};"
        : "+f"(c[0]), "+f"(c[1]), "+f"(c[2]), "+f"(c[3])
        : "r"(a[0]), "r"(a[1]), "r"(a[2]), "r"(a[3]), "r"(b0), "r"(b1));
}

__device__ __forceinline__ void ldsm_x4(uint32_t addr, uint32_t* r) {
    asm volatile("ldmatrix.sync.aligned.m8n8.x4.shared.b16 {%0,%1,%2,%3}, [%4];"
                 : "=r"(r[0]), "=r"(r[1]), "=r"(r[2]), "=r"(r[3]) : "r"(addr));
}

#define CP_ASYNC16(dst, src) \
    asm volatile("cp.async.cg.shared.global [%0], [%1], 16;" :: "r"(dst), "l"(src))
#define CP_COMMIT() asm volatile("cp.async.commit_group;" ::: "memory")
#define CP_WAIT0()  asm volatile("cp.async.wait_group 0;" ::: "memory")

// Packed f16x2 exp2: halves MUFU issue count vs two ex2.approx.f32.
__device__ __forceinline__ void exp2_f16x2(float t0, float t1,
                                           float& p0, float& p1) {
    uint32_t h, e;
    asm("cvt.rn.f16x2.f32 %0, %1, %2;" : "=r"(h) : "f"(t1), "f"(t0));
    asm("ex2.approx.f16x2 %0, %1;" : "=r"(e) : "r"(h));
    asm("{\n\t.reg .b16 lo, hi;\n\t"
        "mov.b32 {lo, hi}, %2;\n\t"
        "cvt.f32.f16 %0, lo;\n\t"
        "cvt.f32.f16 %1, hi;\n\t}"
        : "=f"(p0), "=f"(p1) : "r"(e));
}

// ============================================================================
// K1: convert to bf16, compute pre-scaled norms, pack (cs, w)
// ============================================================================
__global__ void prep_kernel(const float* __restrict__ x,
                            const float* __restrict__ xb,
                            const float* __restrict__ w) {
    const int lid = threadIdx.x & 31;
    #pragma unroll
    for (int pass = 0; pass < 4; pass++) {
        int rowg = blockIdx.x * 8 + (threadIdx.x >> 5) + pass * 4096;
        bool isb = rowg >= KROWS;
        int r    = isb ? rowg - KROWS : rowg;
        const float* src = isb ? xb : x;

        float2 v = ((const float2*)(src + (size_t)r * MDIM))[lid];
        __nv_bfloat162 bv = __float22bfloat162_rn(v);
        __nv_bfloat16* dst = isb ? g_Cb : g_Xb;
        ((__nv_bfloat162*)(dst + (size_t)r * MDIM))[lid] = bv;

        float nrm = v.x * v.x + v.y * v.y;
        #pragma unroll
        for (int o = 16; o; o >>= 1) nrm += __shfl_xor_sync(0xFFFFFFFFu, nrm, o);

        if (lid == 0) {
            float s = -LOG2E * nrm;
            if (isb) g_cw[r] = make_float2(s, w[r]);
            else     g_xs[r] = s;
        }
    }
}

// ============================================================================
// K2: smem-staged bf16 GEMM (mma.sync + ldmatrix + cp.async double buffer)
//     + fused exp/weighted-sum epilogue
// grid = (64 i-tiles, 2 j-splits), 512 threads = 16 warps (4x4 warp grid)
// ============================================================================
#define TI 128
#define TJ 128
#define TPC 32              // j-tiles per CTA: 4096/128
#define TILE_BYTES 16384    // 128 rows x 128 B (64 bf16)

// stage one 128x64-bf16 tile (16 KB) into swizzled smem, 2 cp.async per thread
__device__ __forceinline__ void stage_tile(uint32_t sdst,
                                           const __nv_bfloat16* gsrc, int tid) {
    #pragma unroll
    for (int p = 0; p < 2; p++) {
        int c   = tid + (p << 9);            // 0..1023 16B-chunks
        int row = c >> 3, ch = c & 7;
        uint32_t dst = sdst + (row << 7) + ((ch ^ (row & 7)) << 4);
        const char* src = (const char*)gsrc + (row << 7) + (ch << 4);
        CP_ASYNC16(dst, src);
    }
}

__global__ void __launch_bounds__(512, 1) rbf_main_kernel() {
    __shared__ __align__(1024) uint8_t bufs[2][TILE_BYTES];   // 32 KB
    __shared__ float red[4][TI];

    const int tid = threadIdx.x;
    const int wid = tid >> 5;
    const int lid = tid & 31;
    const int wrow = wid >> 2;           // 0..3 (32-row slice of A)
    const int wc   = wid & 3;            // 0..3 (32-col slice of B)
    const int g    = lid >> 2;           // 0..7
    const int q2   = (lid & 3) * 2;      // 0,2,4,6

    const int i0    = blockIdx.x * TI;
    const int js    = blockIdx.y;
    const int jbase = js * (TJ * TPC);

    const uint32_t sbuf0 = smem_u32(bufs[0]);
    const uint32_t sbuf1 = smem_u32(bufs[1]);

    // ---- stage A into buf1, B tile 0 into buf0 ----
    stage_tile(sbuf1, g_Xb + (size_t)i0 * MDIM, tid);
    stage_tile(sbuf0, g_Cb + (size_t)jbase * MDIM, tid);
    CP_COMMIT();
    CP_WAIT0();
    __syncthreads();

    // ---- extract persistent A fragments from buf1 via ldmatrix ----
    uint32_t a[2][4][4];                 // [mt][ks][reg]
    {
        const int arow_lo = (lid & 7) + ((lid >> 3) & 1) * 8;  // within 16-row frag
        const int chsel   = lid >> 4;                          // k-half chunk
        #pragma unroll
        for (int mt = 0; mt < 2; mt++) {
            #pragma unroll
            for (int ks = 0; ks < 4; ks++) {
                int row = wrow * 32 + mt * 16 + arow_lo;
                int ch  = ks * 2 + chsel;
                uint32_t addr = sbuf1 + (row << 7) + ((ch ^ (row & 7)) << 4);
                ldsm_x4(addr, a[mt][ks]);
            }
        }
    }
    __syncthreads();     // all A reads done before buf1 is reused for B(1)

    // per-thread row exponents
    float xs[2][2];
    #pragma unroll
    for (int mt = 0; mt < 2; mt++) {
        xs[mt][0] = g_xs[i0 + wrow * 32 + mt * 16 + g];
        xs[mt][1] = g_xs[i0 + wrow * 32 + mt * 16 + g + 8];
    }

    const float C2 = 2.0f * LOG2E;
    float acc[2][2] = {{0.f, 0.f}, {0.f, 0.f}};

    // B-ldmatrix lane addressing (constant parts)
    // x4: address lane l feeds matrix (l>>3); matrix pair (m>>1) selects n-octet
    // row = wc*32 + ga*16 + ((l>>4))*8 + (l&7);  chunk parity = (l>>3)&1
    const int brow_lo = wc * 32 + ((lid >> 4) << 3) + (lid & 7);
    const int bch_lo  = (lid >> 3) & 1;                        // k-half within ks

    for (int t = 0; t < TPC; t++) {
        // prefetch next B tile into the other buffer
        if (t + 1 < TPC) {
            uint32_t nb = (t & 1) ? sbuf0 : sbuf1;
            stage_tile(nb, g_Cb + (size_t)(jbase + (t + 1) * TJ) * MDIM, tid);
            CP_COMMIT();
        }
        const uint32_t sb = (t & 1) ? sbuf1 : sbuf0;
        const int j0 = jbase + t * TJ + wc * 32;

        // cw prefetch (broadcast-friendly LDG.128)
        float4 cwv[4];
        #pragma unroll
        for (int nt = 0; nt < 4; nt++)
            cwv[nt] = *(const float4*)(&g_cw[j0 + nt * 8 + q2]);

        // B fragments via ldmatrix, software-pipelined over ks
        uint32_t b[2][4][2];
        #pragma unroll
        for (int ga = 0; ga < 2; ga++) {
            int row = brow_lo + ga * 16;       // covers nt = ga*2 + 0/1
            int ch  = 0 * 2 + bch_lo;
            uint32_t addr = sb + (row << 7) + ((ch ^ (row & 7)) << 4);
            uint32_t r[4]; ldsm_x4(addr, r);
            b[0][ga * 2 + 0][0] = r[0]; b[0][ga * 2 + 0][1] = r[1];
            b[0][ga * 2 + 1][0] = r[2]; b[0][ga * 2 + 1][1] = r[3];
        }

        float c[2][4][4];
        #pragma unroll
        for (int mt = 0; mt < 2; mt++)
            #pragma unroll
            for (int nt = 0; nt < 4; nt++)
                #pragma unroll
                for (int cc = 0; cc < 4; cc++) c[mt][nt][cc] = 0.f;

        #pragma unroll
        for (int ks = 0; ks < 4; ks++) {
            const int cur = ks & 1, nxt = cur ^ 1;
            if (ks < 3) {
                #pragma unroll
                for (int ga = 0; ga < 2; ga++) {
                    int row = brow_lo + ga * 16;
                    int ch  = (ks + 1) * 2 + bch_lo;
                    uint32_t addr = sb + (row << 7) + ((ch ^ (row & 7)) << 4);
                    uint32_t r[4]; ldsm_x4(addr, r);
                    b[nxt][ga * 2 + 0][0] = r[0]; b[nxt][ga * 2 + 0][1] = r[1];
                    b[nxt][ga * 2 + 1][0] = r[2]; b[nxt][ga * 2 + 1][1] = r[3];
                }
            }
            #pragma unroll
            for (int nt = 0; nt < 4; nt++) {
                mma16816(c[0][nt], a[0][ks], b[cur][nt][0], b[cur][nt][1]);
                mma16816(c[1][nt], a[1][ks], b[cur][nt][0], b[cur][nt][1]);
            }
        }

        // ---- epilogue: acc += w_j * 2^(2*log2e*S + xs_i + cs_j) ----
        #pragma unroll
        for (int nt = 0; nt < 4; nt++) {
            const float4 cw = cwv[nt];
            #pragma unroll
            for (int mt = 0; mt < 2; mt++) {
                #pragma unroll
                for (int h = 0; h < 2; h++) {
                    const float base = xs[mt][h];
                    float t0 = fmaf(c[mt][nt][h * 2 + 0], C2, base + cw.x);
                    float t1 = fmaf(c[mt][nt][h * 2 + 1], C2, base + cw.z);
                    float p0, p1;
                    exp2_f16x2(t0, t1, p0, p1);
                    acc[mt][h] = fmaf(p0, cw.y, acc[mt][h]);
                    acc[mt][h] = fmaf(p1, cw.w, acc[mt][h]);
                }
            }
        }

        // make sure next tile landed, and all warps finished reading this one
        if (t + 1 < TPC) CP_WAIT0();
        __syncthreads();
    }

    // ---- reduce cols within quad (lanes in a quad hold disjoint cols) ----
    #pragma unroll
    for (int mt = 0; mt < 2; mt++)
        #pragma unroll
        for (int h = 0; h < 2; h++) {
            float v = acc[mt][h];
            v += __shfl_xor_sync(0xFFFFFFFFu, v, 1);
            v += __shfl_xor_sync(0xFFFFFFFFu, v, 2);
            acc[mt][h] = v;
        }

    if ((lid & 3) == 0) {
        #pragma unroll
        for (int mt = 0; mt < 2; mt++)
            #pragma unroll
            for (int h = 0; h < 2; h++)
                red[wc][wrow * 32 + mt * 16 + g + h * 8] = acc[mt][h];
    }
    __syncthreads();
    if (tid < TI)
        g_partial[js][i0 + tid] =
            (red[0][tid] + red[1][tid]) + (red[2][tid] + red[3][tid]);
}

// ============================================================================
// K3: combine partials + bias + sigmoid
// ============================================================================
__global__ void finish_kernel(const float* __restrict__ b, float* __restrict__ out) {
    int i = blockIdx.x * 256 + threadIdx.x;
    float z = g_partial[0][i] + g_partial[1][i] + b[0];
    out[i] = 1.0f / (1.0f + __expf(-z));
}

// ============================================================================
// kernel_launch
// ============================================================================
extern "C" void kernel_launch(void* const* d_in, const int* in_sizes, int n_in,
                              void* d_out, int out_size) {
    const float* x  = (const float*)d_in[0];
    const float* xb = (const float*)d_in[1];
    const float* w  = (const float*)d_in[2];
    const float* b  = (const float*)d_in[3];
    float* out = (float*)d_out;

    prep_kernel<<<512, 256>>>(x, xb, w);
    dim3 grid(KROWS / TI, 2);
    rbf_main_kernel<<<grid, 512>>>();
    finish_kernel<<<KROWS / 256, 256>>>(b, out);
}

// round 7
// speedup vs baseline: 2.3632x; 1.3462x over previous
#include <cuda_runtime.h>
#include <cuda_fp16.h>
#include <cstdint>

// ============================================================================
// Scratch (static __device__ arrays — no allocations allowed)
// ============================================================================
#define KROWS 8192
#define NROWS 8192
#define MDIM  64

__device__ __half g_Xh[KROWS * MDIM];       // x in f16
__device__ __half g_Ch[NROWS * MDIM];       // x_basis in f16
__device__ __half g_xsh[KROWS];             // -log2e * ||x_i||^2  (f16)
__device__ __half g_csh[NROWS];             // -log2e * ||c_j||^2  (f16)
__device__ __half g_wh[NROWS];              // w_j                 (f16)
__device__ float  g_partial[4][KROWS];      // j-split partial logits

#define LOG2E 1.4426950408889634f

// ============================================================================
// PTX helpers (baseline features only — sm_100 non-'a' target)
// ============================================================================
__device__ __forceinline__ uint32_t smem_u32(const void* p) {
    uint32_t a;
    asm("{ .reg .u64 t; cvta.to.shared.u64 t, %1; cvt.u32.u64 %0, t; }"
        : "=r"(a) : "l"(p));
    return a;
}

// f16 x f16 -> f16 accumulate (2x rate vs f32 accum; D/C are 2 x f16x2 regs)
__device__ __forceinline__ void mma16816_f16(uint32_t& c0, uint32_t& c1,
                                             const uint32_t* a,
                                             uint32_t b0, uint32_t b1) {
    asm volatile(
        "mma.sync.aligned.m16n8k16.row.col.f16.f16.f16.f16 "
        "{%0,%1}, {%2,%3,%4,%5}, {%6,%7}, {%0,%1};"
        : "+r"(c0), "+r"(c1)
        : "r"(a[0]), "r"(a[1]), "r"(a[2]), "r"(a[3]), "r"(b0), "r"(b1));
}

__device__ __forceinline__ void ldsm_x4(uint32_t addr, uint32_t* r) {
    asm volatile("ldmatrix.sync.aligned.m8n8.x4.shared.b16 {%0,%1,%2,%3}, [%4];"
                 : "=r"(r[0]), "=r"(r[1]), "=r"(r[2]), "=r"(r[3]) : "r"(addr));
}

#define CP_ASYNC16(dst, src) \
    asm volatile("cp.async.cg.shared.global [%0], [%1], 16;" :: "r"(dst), "l"(src))
#define CP_COMMIT() asm volatile("cp.async.commit_group;" ::: "memory")
#define CP_WAIT0()  asm volatile("cp.async.wait_group 0;" ::: "memory")

__device__ __forceinline__ uint32_t ex2_h2(uint32_t t) {
    uint32_t e;
    asm("ex2.approx.f16x2 %0, %1;" : "=r"(e) : "r"(t));
    return e;
}

// ============================================================================
// K1: convert to f16, compute pre-scaled norms (f16), pack cs/w
// 1024 blocks x 256 threads; 16 threads per row, float4 each
// ============================================================================
__global__ void prep_kernel(const float* __restrict__ x,
                            const float* __restrict__ xb,
                            const float* __restrict__ w) {
    int idx  = blockIdx.x * 256 + threadIdx.x;
    int row16 = idx >> 4;                 // 0..16383
    int s     = idx & 15;
    bool isb  = row16 >= KROWS;
    int r     = isb ? row16 - KROWS : row16;
    const float* src = isb ? xb : x;

    float4 v = ((const float4*)(src + (size_t)r * MDIM))[s];
    __half2 h01 = __floats2half2_rn(v.x, v.y);
    __half2 h23 = __floats2half2_rn(v.z, v.w);
    __half* dst = isb ? g_Ch : g_Xh;
    uint2 pk;
    pk.x = *(const uint32_t*)&h01;
    pk.y = *(const uint32_t*)&h23;
    ((uint2*)(dst + (size_t)r * MDIM))[s] = pk;

    float nrm = v.x * v.x + v.y * v.y + v.z * v.z + v.w * v.w;
    #pragma unroll
    for (int o = 8; o; o >>= 1) nrm += __shfl_xor_sync(0xFFFFFFFFu, nrm, o);

    if (s == 0) {
        float sc = -LOG2E * nrm;
        if (isb) {
            g_csh[r] = __float2half(sc);
            g_wh[r]  = __float2half(w[r]);
        } else {
            g_xsh[r] = __float2half(sc);
        }
    }
}

// ============================================================================
// K2: smem-staged f16 GEMM (mma.sync f16-accum + ldmatrix + cp.async)
//     + fused f16x2 exp/weighted-sum epilogue
// grid = (64 i-tiles, 4 j-splits) = 256 CTAs, 256 threads = 8 warps
// warp grid: 4 warp-rows (32 A-rows) x 2 warp-cols (64 B-cols)
// 2 CTAs resident per SM -> cross-CTA phase overlap (MMA vs epilogue)
// ============================================================================
#define TI 128
#define TJ 128
#define TPC 16              // j-tiles per CTA: 8192/4/128
#define TILE_BYTES 16384    // 128 rows x 128 B (64 f16)

// stage one 128x64-f16 tile (16 KB) into swizzled smem, 4 cp.async per thread
__device__ __forceinline__ void stage_tile(uint32_t sdst,
                                           const __half* gsrc, int tid) {
    #pragma unroll
    for (int p = 0; p < 4; p++) {
        int c   = tid + (p << 8);            // 0..1023 16B-chunks
        int row = c >> 3, ch = c & 7;
        uint32_t dst = sdst + (row << 7) + ((ch ^ (row & 7)) << 4);
        const char* src = (const char*)gsrc + (row << 7) + (ch << 4);
        CP_ASYNC16(dst, src);
    }
}

__global__ void __launch_bounds__(256, 2) rbf_main_kernel() {
    __shared__ __align__(1024) uint8_t bufs[2][TILE_BYTES];   // 32 KB
    __shared__ float red[2][TI];

    const int tid = threadIdx.x;
    const int wid = tid >> 5;
    const int lid = tid & 31;
    const int wrow = wid >> 1;           // 0..3 (32-row slice of A)
    const int wc   = wid & 1;            // 0..1 (64-col slice of B)
    const int g    = lid >> 2;           // 0..7
    const int q2   = (lid & 3) * 2;      // 0,2,4,6

    const int i0    = blockIdx.x * TI;
    const int js    = blockIdx.y;
    const int jbase = js * (TJ * TPC);

    const uint32_t sbuf0 = smem_u32(bufs[0]);
    const uint32_t sbuf1 = smem_u32(bufs[1]);

    // ---- stage A into buf1, B tile 0 into buf0 ----
    stage_tile(sbuf1, g_Xh + (size_t)i0 * MDIM, tid);
    stage_tile(sbuf0, g_Ch + (size_t)jbase * MDIM, tid);
    CP_COMMIT();
    CP_WAIT0();
    __syncthreads();

    // ---- persistent A fragments from buf1 via ldmatrix ----
    uint32_t a[2][4][4];                 // [mt][ks][reg]
    {
        const int arow_lo = (lid & 7) + ((lid >> 3) & 1) * 8;
        const int chsel   = lid >> 4;
        #pragma unroll
        for (int mt = 0; mt < 2; mt++) {
            #pragma unroll
            for (int ks = 0; ks < 4; ks++) {
                int row = wrow * 32 + mt * 16 + arow_lo;
                int ch  = ks * 2 + chsel;
                uint32_t addr = sbuf1 + (row << 7) + ((ch ^ (row & 7)) << 4);
                ldsm_x4(addr, a[mt][ks]);
            }
        }
    }
    __syncthreads();     // A reads done before buf1 reused for B(1)

    // per-thread row exponent broadcasts (f16x2)
    uint32_t xsb[2][2];
    #pragma unroll
    for (int mt = 0; mt < 2; mt++)
        #pragma unroll
        for (int h = 0; h < 2; h++) {
            __half2 b2 = __half2half2(g_xsh[i0 + wrow * 32 + mt * 16 + g + h * 8]);
            xsb[mt][h] = *(const uint32_t*)&b2;
        }

    const __half2 C2h = __float2half2_rn(2.0f * LOG2E);
    const uint32_t C2u = *(const uint32_t*)&C2h;

    __half2 acc2[2][2];
    #pragma unroll
    for (int mt = 0; mt < 2; mt++)
        #pragma unroll
        for (int h = 0; h < 2; h++) acc2[mt][h] = __float2half2_rn(0.f);

    // B-ldmatrix lane addressing: matrix m = lid>>3, row-octet (m>>1)
    const int brow_lo = wc * 64 + ((lid >> 4) << 3) + (lid & 7);
    const int bch_lo  = (lid >> 3) & 1;

    for (int t = 0; t < TPC; t++) {
        if (t + 1 < TPC) {
            uint32_t nb = (t & 1) ? sbuf0 : sbuf1;
            stage_tile(nb, g_Ch + (size_t)(jbase + (t + 1) * TJ) * MDIM, tid);
            CP_COMMIT();
        }
        const uint32_t sb = (t & 1) ? sbuf1 : sbuf0;
        const int j0 = jbase + t * TJ + wc * 64;

        // ---- MMA: 2 mt x 8 nt, f16 accumulate ----
        uint32_t c[2][8][2];
        #pragma unroll
        for (int mt = 0; mt < 2; mt++)
            #pragma unroll
            for (int nt = 0; nt < 8; nt++) { c[mt][nt][0] = 0u; c[mt][nt][1] = 0u; }

        #pragma unroll
        for (int ks = 0; ks < 4; ks++) {
            uint32_t b[8][2];
            #pragma unroll
            for (int ga = 0; ga < 4; ga++) {
                int row = brow_lo + ga * 16;
                int ch  = ks * 2 + bch_lo;
                uint32_t addr = sb + (row << 7) + ((ch ^ (row & 7)) << 4);
                uint32_t r[4]; ldsm_x4(addr, r);
                b[ga * 2 + 0][0] = r[0]; b[ga * 2 + 0][1] = r[1];
                b[ga * 2 + 1][0] = r[2]; b[ga * 2 + 1][1] = r[3];
            }
            #pragma unroll
            for (int nt = 0; nt < 8; nt++) {
                mma16816_f16(c[0][nt][0], c[0][nt][1], a[0][ks], b[nt][0], b[nt][1]);
                mma16816_f16(c[1][nt][0], c[1][nt][1], a[1][ks], b[nt][0], b[nt][1]);
            }
        }

        // ---- epilogue (all f16x2): acc += w * 2^(C2*S + xs + cs) ----
        #pragma unroll
        for (int nt = 0; nt < 8; nt++) {
            const int jj = j0 + nt * 8 + q2;
            const uint32_t cs2 = *(const uint32_t*)(g_csh + jj);
            const uint32_t w2  = *(const uint32_t*)(g_wh + jj);
            const __half2 cs2h = *(const __half2*)&cs2;
            const __half2 w2h  = *(const __half2*)&w2;
            #pragma unroll
            for (int mt = 0; mt < 2; mt++) {
                #pragma unroll
                for (int h = 0; h < 2; h++) {
                    __half2 base = __hadd2(*(const __half2*)&xsb[mt][h], cs2h);
                    __half2 cc   = *(const __half2*)&c[mt][nt][h];
                    __half2 t2   = __hfma2(cc, *(const __half2*)&C2u, base);
                    uint32_t e   = ex2_h2(*(const uint32_t*)&t2);
                    acc2[mt][h]  = __hfma2(*(const __half2*)&e, w2h, acc2[mt][h]);
                }
            }
        }

        if (t + 1 < TPC) CP_WAIT0();
        __syncthreads();
    }

    // ---- reduce: cols within quad, then across warp-cols via smem ----
    float accf[2][2];
    #pragma unroll
    for (int mt = 0; mt < 2; mt++)
        #pragma unroll
        for (int h = 0; h < 2; h++) {
            float v = __low2float(acc2[mt][h]) + __high2float(acc2[mt][h]);
            v += __shfl_xor_sync(0xFFFFFFFFu, v, 1);
            v += __shfl_xor_sync(0xFFFFFFFFu, v, 2);
            accf[mt][h] = v;
        }

    if ((lid & 3) == 0) {
        #pragma unroll
        for (int mt = 0; mt < 2; mt++)
            #pragma unroll
            for (int h = 0; h < 2; h++)
                red[wc][wrow * 32 + mt * 16 + g + h * 8] = accf[mt][h];
    }
    __syncthreads();
    if (tid < TI)
        g_partial[js][i0 + tid] = red[0][tid] + red[1][tid];
}

// ============================================================================
// K3: combine partials + bias + sigmoid
// ============================================================================
__global__ void finish_kernel(const float* __restrict__ b, float* __restrict__ out) {
    int i = blockIdx.x * 256 + threadIdx.x;
    float z = (g_partial[0][i] + g_partial[1][i])
            + (g_partial[2][i] + g_partial[3][i]) + b[0];
    out[i] = 1.0f / (1.0f + __expf(-z));
}

// ============================================================================
// kernel_launch
// ============================================================================
extern "C" void kernel_launch(void* const* d_in, const int* in_sizes, int n_in,
                              void* d_out, int out_size) {
    const float* x  = (const float*)d_in[0];
    const float* xb = (const float*)d_in[1];
    const float* w  = (const float*)d_in[2];
    const float* b  = (const float*)d_in[3];
    float* out = (float*)d_out;

    prep_kernel<<<1024, 256>>>(x, xb, w);
    dim3 grid(KROWS / TI, 4);
    rbf_main_kernel<<<grid, 256>>>();
    finish_kernel<<<KROWS / 256, 256>>>(b, out);
}